// round 5
// baseline (speedup 1.0000x reference)
#include <cuda_runtime.h>
#include <math.h>

#define Nn 2048
#define Uu 64
#define ALPHA 1.0f
#define KCH 16            // split-K chunks in the aggregation GEMM
#define RST 68            // smem row stride (64 + 4 pad) in floats

// ---------------- scratch (no allocations allowed) ----------------
__device__ float g_L[(size_t)Nn * Nn];                 // 16 MB: E = exp(logits)
__device__ float g_colpart[256 * Nn];                  // partial column sums (2 MB)
__device__ float g_colinv[Nn];                         // 1 / column sum
__device__ float g_head[Nn];
__device__ float g_oppart[KCH * (size_t)Nn * Uu];      // split-K partials (8 MB)
__device__ float g_rr[Nn];                             // return ratio per row

// packed dual-fp32 FMA (Blackwell f32x2 pipe, PTX-only)
__device__ __forceinline__ void ffma2(unsigned long long& d,
                                      unsigned long long a,
                                      unsigned long long b) {
    asm("fma.rn.f32x2 %0, %1, %2, %0;" : "+l"(d) : "l"(a), "l"(b));
}
__device__ __forceinline__ unsigned long long pack2(float x) {
    unsigned long long r;
    asm("mov.b64 %0, {%1, %1};" : "=l"(r) : "r"(__float_as_uint(x)));
    return r;
}

// ---------------- K1: head scores ----------------
__global__ void k_init(const float* __restrict__ feature,
                       const float* __restrict__ head_w,
                       const float* __restrict__ head_b) {
    int i = blockIdx.x * blockDim.x + threadIdx.x;
    if (i >= Nn) return;
    const float4* fr = (const float4*)(feature + (size_t)i * Uu);
    const float4* hw = (const float4*)head_w;
    float4 a4 = make_float4(0.f, 0.f, 0.f, 0.f);
#pragma unroll
    for (int k = 0; k < 16; k++) {
        float4 a = fr[k], w = hw[k];
        a4.x += a.x * w.x; a4.y += a.y * w.y; a4.z += a.z * w.z; a4.w += a.w * w.w;
    }
    g_head[i] = fmaxf((a4.x + a4.y) + (a4.z + a4.w) + head_b[0], 0.f);
}

// ---------------- K2: 1 GiB stream, fused logit + exp + partial colsum ------
// Block: 128 threads, owns 8 rows x 128 cols. Double-buffered smem tiles,
// register prefetch of next row-tile overlaps compute. Thread t owns column
// j0+t and accumulates its 8-row partial sum -> g_colpart (kills colpart pass).
// Softmax max-subtraction skipped: logits bounded well under exp overflow.
__global__ void k_rel_exp(const float* __restrict__ relation,
                          const float* __restrict__ rel_w,
                          const float* __restrict__ rel_b,
                          const float* __restrict__ rel_mask) {
    extern __shared__ float s_tile[];        // 2 * 128 * RST floats = 69632 B
    __shared__ float s_w[64];

    const int t  = threadIdx.x;
    const int j0 = blockIdx.x * 128;
    const int i0 = blockIdx.y * 8;
    if (t < 16) ((float4*)s_w)[t] = ((const float4*)rel_w)[t];

    const float4* src = (const float4*)relation + ((size_t)i0 * Nn + j0) * 16;
    const float  rb   = rel_b[0];

    // prefetch row-tile 0 into registers (coalesced flat)
    float4 v[16];
#pragma unroll
    for (int k = 0; k < 16; k++) v[k] = src[k * 128 + t];

    float colsum = 0.f;
#pragma unroll
    for (int r = 0; r < 8; r++) {
        float* buf = s_tile + (r & 1) * (128 * RST);
        // stash prefetched tile (flat idx -> padded rows)
#pragma unroll
        for (int k = 0; k < 16; k++) {
            int idx = k * 128 + t;
            *(float4*)&buf[(idx >> 4) * RST + (idx & 15) * 4] = v[k];
        }
        __syncthreads();
        // prefetch next row-tile (overlaps the compute below)
        if (r < 7) {
            const float4* s2 = src + (size_t)(r + 1) * Nn * 16;
#pragma unroll
            for (int k = 0; k < 16; k++) v[k] = s2[k * 128 + t];
        }
        // dot own pair row with w (conflict-free: 272 B row stride)
        const float* rowp = &buf[t * RST];
        float4 a4 = make_float4(0.f, 0.f, 0.f, 0.f);
#pragma unroll
        for (int k = 0; k < 16; k++) {
            float4 a = *(const float4*)&rowp[k * 4];
            float4 w = *(const float4*)&s_w[k * 4];
            a4.x += a.x * w.x; a4.y += a.y * w.y; a4.z += a.z * w.z; a4.w += a.w * w.w;
        }
        float acc = (a4.x + a4.y) + (a4.z + a4.w);
        size_t p = (size_t)(i0 + r) * Nn + j0 + t;
        float logit = fmaxf(acc + rb, 0.f) + rel_mask[p] + g_head[i0 + r];
        float e = __expf(logit);
        g_L[p] = e;
        colsum += e;
    }
    g_colpart[blockIdx.y * Nn + j0 + t] = colsum;
}

// ---------------- K3: reduce 256 partials -> 1/S_j ----------------
// 32 blocks x 256 threads: (64 cols) x (4 chunk groups of 64 partials)
__global__ void k_colfin() {
    __shared__ float s_red[4][64];
    const int t  = threadIdx.x;
    const int jl = t & 63;
    const int cg = t >> 6;
    const int j  = blockIdx.x * 64 + jl;
    float s = 0.f;
#pragma unroll 8
    for (int k = 0; k < 64; k++)
        s += g_colpart[(size_t)(cg * 64 + k) * Nn + j];
    s_red[cg][jl] = s;
    __syncthreads();
    if (t < 64) {
        float tot = s_red[0][t] + s_red[1][t] + s_red[2][t] + s_red[3][t];
        g_colinv[blockIdx.x * 64 + t] = 1.0f / tot;
    }
}

// ---------------- K4: split-K GEMM  op = E @ (feature * colinv) ----------------
// grid (32 row-blocks, KCH j-chunks of 128), 256 threads, 64x64 block,
// 4x4 register tiles computed with packed f32x2 FMAs.
__global__ void k_gemm(const float* __restrict__ feature) {
    __shared__ float Es[64][65];
    __shared__ float fs[64][68];

    const int t  = threadIdx.x;
    const int ug = t & 15;          // u0 = ug*4
    const int rg = t >> 4;          // r0 = rg*4
    const int i0 = blockIdx.x * 64;
    const int jc = blockIdx.y;

    unsigned long long acc[4][2];
#pragma unroll
    for (int r = 0; r < 4; r++) { acc[r][0] = 0ull; acc[r][1] = 0ull; }

#pragma unroll
    for (int tile = 0; tile < 2; tile++) {
        const int j0 = jc * 128 + tile * 64;
#pragma unroll
        for (int k = 0; k < 16; k++) {
            int q = k * 256 + t;
            int r = q >> 6, c = q & 63;
            Es[r][c] = g_L[(size_t)(i0 + r) * Nn + (j0 + c)];
        }
#pragma unroll
        for (int k = 0; k < 16; k++) {
            int q = k * 256 + t;
            int jr = q >> 6, u = q & 63;
            fs[jr][u] = feature[(size_t)(j0 + jr) * Uu + u] * g_colinv[j0 + jr];
        }
        __syncthreads();
#pragma unroll
        for (int jj = 0; jj < 64; jj++) {
            ulonglong2 bb = *(const ulonglong2*)&fs[jj][ug * 4];
            unsigned long long a0 = pack2(Es[rg * 4 + 0][jj]);
            unsigned long long a1 = pack2(Es[rg * 4 + 1][jj]);
            unsigned long long a2 = pack2(Es[rg * 4 + 2][jj]);
            unsigned long long a3 = pack2(Es[rg * 4 + 3][jj]);
            ffma2(acc[0][0], a0, bb.x); ffma2(acc[0][1], a0, bb.y);
            ffma2(acc[1][0], a1, bb.x); ffma2(acc[1][1], a1, bb.y);
            ffma2(acc[2][0], a2, bb.x); ffma2(acc[2][1], a2, bb.y);
            ffma2(acc[3][0], a3, bb.x); ffma2(acc[3][1], a3, bb.y);
        }
        __syncthreads();
    }
    size_t base = (size_t)jc * Nn * Uu;
#pragma unroll
    for (int r = 0; r < 4; r++) {
        *(ulonglong2*)&g_oppart[base + (size_t)(i0 + rg * 4 + r) * Uu + ug * 4] =
            make_ulonglong2(acc[r][0], acc[r][1]);
    }
}

// ---------------- K5: prediction + return ratio ----------------
__global__ void k_pred(const float* __restrict__ feature,
                       const float* __restrict__ pred_w,
                       const float* __restrict__ pred_b,
                       const float* __restrict__ base_price) {
    int i = blockIdx.x * blockDim.x + threadIdx.x;
    if (i >= Nn) return;
    float dot = pred_b[0];
    const float4* fr  = (const float4*)(feature + (size_t)i * Uu);
    const float4* pw  = (const float4*)pred_w;
    const float4* pw2 = (const float4*)(pred_w + Uu);
#pragma unroll
    for (int k = 0; k < 16; k++) {
        float4 a = fr[k], w = pw[k];
        dot += a.x * w.x + a.y * w.y + a.z * w.z + a.w * w.w;
    }
#pragma unroll
    for (int k = 0; k < 16; k++) {
        float4 s = make_float4(0.f, 0.f, 0.f, 0.f);
#pragma unroll
        for (int c = 0; c < KCH; c++) {
            float4 v = *(const float4*)&g_oppart[(size_t)c * Nn * Uu + (size_t)i * Uu + k * 4];
            s.x += v.x; s.y += v.y; s.z += v.z; s.w += v.w;
        }
        float4 w = pw2[k];
        dot += s.x * w.x + s.y * w.y + s.z * w.z + s.w * w.w;
    }
    float pred = dot >= 0.f ? dot : 0.2f * dot;
    float bp = base_price[i];
    g_rr[i] = (pred - bp) / bp;
}

// ---------------- K6: final losses (single block) ----------------
__global__ void k_final(const float* __restrict__ ground_truth,
                        const float* __restrict__ mask,
                        float* __restrict__ out, int out_size) {
    __shared__ float s_reg[256], s_p[256], s_n[256];
    int t = threadIdx.x;
    float reg = 0.f, p = 0.f, ng = 0.f;
    for (int i = t; i < Nn; i += 256) {
        float rr = g_rr[i];
        float d = rr - ground_truth[i];
        reg += d * d;
        float x = rr * mask[i];
        p  += fmaxf(x, 0.f);
        ng += fminf(x, 0.f);
    }
    s_reg[t] = reg; s_p[t] = p; s_n[t] = ng;
    __syncthreads();
    for (int st = 128; st > 0; st >>= 1) {
        if (t < st) {
            s_reg[t] += s_reg[t + st];
            s_p[t]   += s_p[t + st];
            s_n[t]   += s_n[t + st];
        }
        __syncthreads();
    }
    if (t == 0) {
        float regl = s_reg[0];
        float P = s_p[0], Ng = s_n[0];
        float rank = (P * P + Ng * Ng) / ((float)Nn * (float)Nn);
        float loss = regl + ALPHA * rank;
        if (out_size >= 1) out[0] = loss;
        if (out_size >= 2) out[1] = regl;
        if (out_size >= 3) out[2] = rank;
    }
}

// ---------------- launch ----------------
extern "C" void kernel_launch(void* const* d_in, const int* in_sizes, int n_in,
                              void* d_out, int out_size) {
    const float* feature      = (const float*)d_in[0];
    const float* relation     = (const float*)d_in[1];
    const float* rel_mask     = (const float*)d_in[2];
    const float* base_price   = (const float*)d_in[3];
    const float* ground_truth = (const float*)d_in[4];
    const float* mask         = (const float*)d_in[5];
    const float* rel_w        = (const float*)d_in[6];
    const float* rel_b        = (const float*)d_in[7];
    const float* head_w       = (const float*)d_in[8];
    const float* head_b       = (const float*)d_in[9];
    // tail_w/tail_b (10/11) dead: tail[j] constant per softmax column (axis 0)
    const float* pred_w       = (const float*)d_in[12];
    const float* pred_b       = (const float*)d_in[13];
    float* out = (float*)d_out;

    const int relsmem = 2 * 128 * RST * (int)sizeof(float);   // 69632 B
    cudaFuncSetAttribute(k_rel_exp, cudaFuncAttributeMaxDynamicSharedMemorySize, relsmem);

    k_init<<<(Nn + 255) / 256, 256>>>(feature, head_w, head_b);
    {
        dim3 g(Nn / 128, Nn / 8);          // 16 x 256 blocks
        k_rel_exp<<<g, 128, relsmem>>>(relation, rel_w, rel_b, rel_mask);
    }
    k_colfin<<<Nn / 64, 256>>>();
    {
        dim3 g(Nn / 64, KCH);
        k_gemm<<<g, 256>>>(feature);
    }
    k_pred<<<(Nn + 255) / 256, 256>>>(feature, pred_w, pred_b, base_price);
    k_final<<<1, 256>>>(ground_truth, mask, out, out_size);
}

// round 6
// speedup vs baseline: 1.1329x; 1.1329x over previous
#include <cuda_runtime.h>
#include <math.h>

#define Nn 2048
#define Uu 64
#define ALPHA 1.0f
#define KCH 16            // split-K chunks in the aggregation GEMM

// ---------------- scratch (no allocations allowed) ----------------
__device__ float g_L[(size_t)Nn * Nn];                 // 16 MB: E = exp(logits)
__device__ float g_colpart[32 * Nn];                   // partial column sums
__device__ float g_colinv[Nn];                         // 1 / column sum
__device__ float g_head[Nn];
__device__ float g_oppart[KCH * (size_t)Nn * Uu];      // split-K partials (8 MB)
__device__ float g_rr[Nn];                             // return ratio per row

// ---------------- K1: head scores ----------------
__global__ void k_init(const float* __restrict__ feature,
                       const float* __restrict__ head_w,
                       const float* __restrict__ head_b) {
    int i = blockIdx.x * blockDim.x + threadIdx.x;
    if (i >= Nn) return;
    const float4* fr = (const float4*)(feature + (size_t)i * Uu);
    const float4* hw = (const float4*)head_w;
    float4 a4 = make_float4(0.f, 0.f, 0.f, 0.f);
#pragma unroll
    for (int k = 0; k < 16; k++) {
        float4 a = fr[k], w = hw[k];
        a4.x += a.x * w.x; a4.y += a.y * w.y; a4.z += a.z * w.z; a4.w += a.w * w.w;
    }
    g_head[i] = fmaxf((a4.x + a4.y) + (a4.z + a4.w) + head_b[0], 0.f);
}

// ---------------- K2: 1 GiB stream, warp-cooperative, fused exp + colsum ----
// 8 lanes per pair, 4 pairs per warp -> each warp-iteration reads 1KB
// contiguous (64 consecutive float4). No smem, no syncs in hot loop.
// E[i,j] = exp( relu(rel[i,j,:]·w + b) + mask[i,j] + head[i] )
// (max-subtraction skipped: logits bounded far below fp32 exp overflow)
__global__ void k_rel_exp(const float* __restrict__ relation,
                          const float* __restrict__ rel_w,
                          const float* __restrict__ rel_b,
                          const float* __restrict__ rel_mask) {
    __shared__ float s_head[64];
    const int t  = threadIdx.x;
    const int w  = t >> 5;          // warp in block (0-7)
    const int l  = t & 31;          // lane
    const int g  = l >> 3;          // pair group within warp (0-3)
    const int k  = l & 7;           // element slot within pair
    const int j0 = blockIdx.x * 32 + w * 4;   // warp's 4 columns
    const int i0 = blockIdx.y * 64;           // block's 64 rows

    if (t < 64) s_head[t] = g_head[i0 + t];
    __syncthreads();

    const float rb = rel_b[0];
    const float4 wa = __ldg(&((const float4*)rel_w)[k]);
    const float4 wb = __ldg(&((const float4*)rel_w)[k + 8]);

    const float4* base = (const float4*)relation + ((size_t)i0 * Nn + j0) * 16;
    const int o1 = g * 16 + k;      // lane's fixed float4 offsets in 1KB span
    const int o2 = o1 + 8;

    float colsum = 0.f;
#pragma unroll 4
    for (int r = 0; r < 64; r++) {
        const float4* rowp = base + (size_t)r * (Nn * 16);
        float4 a = rowp[o1];
        float4 b = rowp[o2];
        float d = a.x * wa.x + a.y * wa.y + a.z * wa.z + a.w * wa.w
                + b.x * wb.x + b.y * wb.y + b.z * wb.z + b.w * wb.w;
        // reduce over the 8-lane group
        d += __shfl_xor_sync(0xffffffffu, d, 1);
        d += __shfl_xor_sync(0xffffffffu, d, 2);
        d += __shfl_xor_sync(0xffffffffu, d, 4);
        // gather the 4 group sums into lanes 0-3
        float s = __shfl_sync(0xffffffffu, d, (l * 8) & 31);
        if (l < 4) {
            size_t p = (size_t)(i0 + r) * Nn + j0 + l;
            float logit = fmaxf(s + rb, 0.f) + rel_mask[p] + s_head[r];
            float e = __expf(logit);
            g_L[p] = e;
            colsum += e;
        }
    }
    if (l < 4)
        g_colpart[(size_t)blockIdx.y * Nn + j0 + l] = colsum;
}

// ---------------- K3: reduce 32 partials -> 1/S_j ----------------
__global__ void k_colfin() {
    int j = blockIdx.x * 256 + threadIdx.x;
    float s = 0.f;
#pragma unroll
    for (int c = 0; c < 32; c++) s += g_colpart[(size_t)c * Nn + j];
    g_colinv[j] = 1.0f / s;
}

// ---------------- K4: split-K GEMM  op = E @ (feature * colinv) ----------------
// grid (32 row-blocks, KCH j-chunks of 128), 256 threads, 64x64 block, 4x4 reg tiles
__global__ void k_gemm(const float* __restrict__ feature) {
    __shared__ float Es[64][65];
    __shared__ float fs[64][68];

    const int t  = threadIdx.x;
    const int ug = t & 15;          // u0 = ug*4
    const int rg = t >> 4;          // r0 = rg*4
    const int i0 = blockIdx.x * 64;
    const int jc = blockIdx.y;

    float4 acc[4];
#pragma unroll
    for (int r = 0; r < 4; r++) acc[r] = make_float4(0.f, 0.f, 0.f, 0.f);

#pragma unroll
    for (int tile = 0; tile < 2; tile++) {
        const int j0 = jc * 128 + tile * 64;
#pragma unroll
        for (int k = 0; k < 16; k++) {
            int q = k * 256 + t;
            int r = q >> 6, c = q & 63;
            Es[r][c] = g_L[(size_t)(i0 + r) * Nn + (j0 + c)];
        }
#pragma unroll
        for (int k = 0; k < 16; k++) {
            int q = k * 256 + t;
            int jr = q >> 6, u = q & 63;
            fs[jr][u] = feature[(size_t)(j0 + jr) * Uu + u] * g_colinv[j0 + jr];
        }
        __syncthreads();
#pragma unroll
        for (int jj = 0; jj < 64; jj++) {
            float4 b = *(const float4*)&fs[jj][ug * 4];
            float a0 = Es[rg * 4 + 0][jj];
            float a1 = Es[rg * 4 + 1][jj];
            float a2 = Es[rg * 4 + 2][jj];
            float a3 = Es[rg * 4 + 3][jj];
            acc[0].x += a0 * b.x; acc[0].y += a0 * b.y; acc[0].z += a0 * b.z; acc[0].w += a0 * b.w;
            acc[1].x += a1 * b.x; acc[1].y += a1 * b.y; acc[1].z += a1 * b.z; acc[1].w += a1 * b.w;
            acc[2].x += a2 * b.x; acc[2].y += a2 * b.y; acc[2].z += a2 * b.z; acc[2].w += a2 * b.w;
            acc[3].x += a3 * b.x; acc[3].y += a3 * b.y; acc[3].z += a3 * b.z; acc[3].w += a3 * b.w;
        }
        __syncthreads();
    }
    size_t base = (size_t)jc * Nn * Uu;
#pragma unroll
    for (int r = 0; r < 4; r++) {
        *(float4*)&g_oppart[base + (size_t)(i0 + rg * 4 + r) * Uu + ug * 4] = acc[r];
    }
}

// ---------------- K5: prediction + return ratio ----------------
__global__ void k_pred(const float* __restrict__ feature,
                       const float* __restrict__ pred_w,
                       const float* __restrict__ pred_b,
                       const float* __restrict__ base_price) {
    int i = blockIdx.x * blockDim.x + threadIdx.x;
    if (i >= Nn) return;
    float dot = pred_b[0];
    const float4* fr  = (const float4*)(feature + (size_t)i * Uu);
    const float4* pw  = (const float4*)pred_w;
    const float4* pw2 = (const float4*)(pred_w + Uu);
#pragma unroll
    for (int k = 0; k < 16; k++) {
        float4 a = fr[k], w = pw[k];
        dot += a.x * w.x + a.y * w.y + a.z * w.z + a.w * w.w;
    }
#pragma unroll
    for (int k = 0; k < 16; k++) {
        float4 s = make_float4(0.f, 0.f, 0.f, 0.f);
#pragma unroll
        for (int c = 0; c < KCH; c++) {
            float4 v = *(const float4*)&g_oppart[(size_t)c * Nn * Uu + (size_t)i * Uu + k * 4];
            s.x += v.x; s.y += v.y; s.z += v.z; s.w += v.w;
        }
        float4 w = pw2[k];
        dot += s.x * w.x + s.y * w.y + s.z * w.z + s.w * w.w;
    }
    float pred = dot >= 0.f ? dot : 0.2f * dot;
    float bp = base_price[i];
    g_rr[i] = (pred - bp) / bp;
}

// ---------------- K6: final losses (single block) ----------------
__global__ void k_final(const float* __restrict__ ground_truth,
                        const float* __restrict__ mask,
                        float* __restrict__ out, int out_size) {
    __shared__ float s_reg[256], s_p[256], s_n[256];
    int t = threadIdx.x;
    float reg = 0.f, p = 0.f, ng = 0.f;
    for (int i = t; i < Nn; i += 256) {
        float rr = g_rr[i];
        float d = rr - ground_truth[i];
        reg += d * d;
        float x = rr * mask[i];
        p  += fmaxf(x, 0.f);
        ng += fminf(x, 0.f);
    }
    s_reg[t] = reg; s_p[t] = p; s_n[t] = ng;
    __syncthreads();
    for (int st = 128; st > 0; st >>= 1) {
        if (t < st) {
            s_reg[t] += s_reg[t + st];
            s_p[t]   += s_p[t + st];
            s_n[t]   += s_n[t + st];
        }
        __syncthreads();
    }
    if (t == 0) {
        float regl = s_reg[0];
        float P = s_p[0], Ng = s_n[0];
        float rank = (P * P + Ng * Ng) / ((float)Nn * (float)Nn);
        float loss = regl + ALPHA * rank;
        if (out_size >= 1) out[0] = loss;
        if (out_size >= 2) out[1] = regl;
        if (out_size >= 3) out[2] = rank;
    }
}

// ---------------- launch ----------------
extern "C" void kernel_launch(void* const* d_in, const int* in_sizes, int n_in,
                              void* d_out, int out_size) {
    const float* feature      = (const float*)d_in[0];
    const float* relation     = (const float*)d_in[1];
    const float* rel_mask     = (const float*)d_in[2];
    const float* base_price   = (const float*)d_in[3];
    const float* ground_truth = (const float*)d_in[4];
    const float* mask         = (const float*)d_in[5];
    const float* rel_w        = (const float*)d_in[6];
    const float* rel_b        = (const float*)d_in[7];
    const float* head_w       = (const float*)d_in[8];
    const float* head_b       = (const float*)d_in[9];
    // tail_w/tail_b (10/11) dead: tail[j] constant per softmax column (axis 0)
    const float* pred_w       = (const float*)d_in[12];
    const float* pred_b       = (const float*)d_in[13];
    float* out = (float*)d_out;

    k_init<<<(Nn + 255) / 256, 256>>>(feature, head_w, head_b);
    {
        dim3 g(Nn / 32, Nn / 64);          // 64 x 32 = 2048 blocks
        k_rel_exp<<<g, 256>>>(relation, rel_w, rel_b, rel_mask);
    }
    k_colfin<<<Nn / 256, 256>>>();
    {
        dim3 g(Nn / 64, KCH);
        k_gemm<<<g, 256>>>(feature);
    }
    k_pred<<<(Nn + 255) / 256, 256>>>(feature, pred_w, pred_b, base_price);
    k_final<<<1, 256>>>(ground_truth, mask, out, out_size);
}

// round 7
// speedup vs baseline: 1.2020x; 1.0610x over previous
#include <cuda_runtime.h>
#include <math.h>

#define Nn 2048
#define Uu 64
#define ALPHA 1.0f
#define KCH 8             // split-K chunks in the aggregation GEMM

// ---------------- scratch (no allocations allowed) ----------------
__device__ float g_L[(size_t)Nn * Nn];                 // 16 MB: E = exp(logits)
__device__ float g_colpart[32 * Nn];                   // partial column sums
__device__ float g_head[Nn];
__device__ float g_oppart[KCH * (size_t)Nn * Uu];      // split-K partials (4 MB)
__device__ float g_rr[Nn];                             // return ratio per row

// ---------------- K1: head scores ----------------
__global__ void k_init(const float* __restrict__ feature,
                       const float* __restrict__ head_w,
                       const float* __restrict__ head_b) {
    int i = blockIdx.x * blockDim.x + threadIdx.x;
    if (i >= Nn) return;
    const float4* fr = (const float4*)(feature + (size_t)i * Uu);
    const float4* hw = (const float4*)head_w;
    float4 a4 = make_float4(0.f, 0.f, 0.f, 0.f);
#pragma unroll
    for (int k = 0; k < 16; k++) {
        float4 a = fr[k], w = hw[k];
        a4.x += a.x * w.x; a4.y += a.y * w.y; a4.z += a.z * w.z; a4.w += a.w * w.w;
    }
    g_head[i] = fmaxf((a4.x + a4.y) + (a4.z + a4.w) + head_b[0], 0.f);
}

// ---------------- K2: 1 GiB stream, warp-cooperative, fused exp + colsum ----
// 8 lanes per pair, 4 pairs per warp -> each warp-iteration reads 1KB
// contiguous (64 consecutive float4). No smem, no syncs in hot loop.
// E[i,j] = exp( relu(rel[i,j,:]·w + b) + mask[i,j] + head[i] )
// (max-subtraction skipped: logits bounded far below fp32 exp overflow)
__global__ void k_rel_exp(const float* __restrict__ relation,
                          const float* __restrict__ rel_w,
                          const float* __restrict__ rel_b,
                          const float* __restrict__ rel_mask) {
    __shared__ float s_head[64];
    const int t  = threadIdx.x;
    const int w  = t >> 5;          // warp in block (0-7)
    const int l  = t & 31;          // lane
    const int g  = l >> 3;          // pair group within warp (0-3)
    const int k  = l & 7;           // element slot within pair
    const int j0 = blockIdx.x * 32 + w * 4;   // warp's 4 columns
    const int i0 = blockIdx.y * 64;           // block's 64 rows

    if (t < 64) s_head[t] = g_head[i0 + t];
    __syncthreads();

    const float rb = rel_b[0];
    const float4 wa = __ldg(&((const float4*)rel_w)[k]);
    const float4 wb = __ldg(&((const float4*)rel_w)[k + 8]);

    const float4* base = (const float4*)relation + ((size_t)i0 * Nn + j0) * 16;
    const int o1 = g * 16 + k;      // lane's fixed float4 offsets in 1KB span
    const int o2 = o1 + 8;

    float colsum = 0.f;
#pragma unroll 4
    for (int r = 0; r < 64; r++) {
        const float4* rowp = base + (size_t)r * (Nn * 16);
        float4 a = rowp[o1];
        float4 b = rowp[o2];
        float d = a.x * wa.x + a.y * wa.y + a.z * wa.z + a.w * wa.w
                + b.x * wb.x + b.y * wb.y + b.z * wb.z + b.w * wb.w;
        // reduce over the 8-lane group
        d += __shfl_xor_sync(0xffffffffu, d, 1);
        d += __shfl_xor_sync(0xffffffffu, d, 2);
        d += __shfl_xor_sync(0xffffffffu, d, 4);
        // gather the 4 group sums into lanes 0-3
        float s = __shfl_sync(0xffffffffu, d, (l * 8) & 31);
        if (l < 4) {
            size_t p = (size_t)(i0 + r) * Nn + j0 + l;
            float logit = fmaxf(s + rb, 0.f) + rel_mask[p] + s_head[r];
            float e = __expf(logit);
            g_L[p] = e;
            colsum += e;
        }
    }
    if (l < 4)
        g_colpart[(size_t)blockIdx.y * Nn + j0 + l] = colsum;
}

// ---------------- K3: split-K GEMM  op = E @ (feature * colinv) ----------------
// grid (32 row-blocks, KCH j-chunks of 256), 256 threads, 64x64 block,
// 4x4 reg tiles. colinv reduced from partials in the prologue (no extra kernel).
__global__ void __launch_bounds__(256, 2) k_gemm(const float* __restrict__ feature) {
    __shared__ float Es[64][65];
    __shared__ float fs[64][68];
    __shared__ float s_cinv[256];

    const int t  = threadIdx.x;
    const int ug = t & 15;          // u0 = ug*4
    const int rg = t >> 4;          // r0 = rg*4
    const int i0 = blockIdx.x * 64;
    const int jc = blockIdx.y;

    // prologue: colinv for this block's 256 columns
    {
        int j = jc * 256 + t;
        float s = 0.f;
#pragma unroll
        for (int c = 0; c < 32; c++) s += g_colpart[(size_t)c * Nn + j];
        s_cinv[t] = 1.0f / s;
    }
    __syncthreads();

    float4 acc[4];
#pragma unroll
    for (int r = 0; r < 4; r++) acc[r] = make_float4(0.f, 0.f, 0.f, 0.f);

#pragma unroll
    for (int tile = 0; tile < 4; tile++) {
        const int j0 = jc * 256 + tile * 64;
#pragma unroll
        for (int k = 0; k < 16; k++) {
            int q = k * 256 + t;
            int r = q >> 6, c = q & 63;
            Es[r][c] = g_L[(size_t)(i0 + r) * Nn + (j0 + c)];
        }
#pragma unroll
        for (int k = 0; k < 16; k++) {
            int q = k * 256 + t;
            int jr = q >> 6, u = q & 63;
            fs[jr][u] = feature[(size_t)(j0 + jr) * Uu + u] * s_cinv[tile * 64 + jr];
        }
        __syncthreads();
#pragma unroll
        for (int jj = 0; jj < 64; jj++) {
            float4 b = *(const float4*)&fs[jj][ug * 4];
            float a0 = Es[rg * 4 + 0][jj];
            float a1 = Es[rg * 4 + 1][jj];
            float a2 = Es[rg * 4 + 2][jj];
            float a3 = Es[rg * 4 + 3][jj];
            acc[0].x += a0 * b.x; acc[0].y += a0 * b.y; acc[0].z += a0 * b.z; acc[0].w += a0 * b.w;
            acc[1].x += a1 * b.x; acc[1].y += a1 * b.y; acc[1].z += a1 * b.z; acc[1].w += a1 * b.w;
            acc[2].x += a2 * b.x; acc[2].y += a2 * b.y; acc[2].z += a2 * b.z; acc[2].w += a2 * b.w;
            acc[3].x += a3 * b.x; acc[3].y += a3 * b.y; acc[3].z += a3 * b.z; acc[3].w += a3 * b.w;
        }
        __syncthreads();
    }
    size_t base = (size_t)jc * Nn * Uu;
#pragma unroll
    for (int r = 0; r < 4; r++) {
        *(float4*)&g_oppart[base + (size_t)(i0 + rg * 4 + r) * Uu + ug * 4] = acc[r];
    }
}

// ---------------- K4: prediction + return ratio ----------------
__global__ void k_pred(const float* __restrict__ feature,
                       const float* __restrict__ pred_w,
                       const float* __restrict__ pred_b,
                       const float* __restrict__ base_price) {
    int i = blockIdx.x * blockDim.x + threadIdx.x;
    if (i >= Nn) return;
    float dot = pred_b[0];
    const float4* fr  = (const float4*)(feature + (size_t)i * Uu);
    const float4* pw  = (const float4*)pred_w;
    const float4* pw2 = (const float4*)(pred_w + Uu);
#pragma unroll
    for (int k = 0; k < 16; k++) {
        float4 a = fr[k], w = pw[k];
        dot += a.x * w.x + a.y * w.y + a.z * w.z + a.w * w.w;
    }
#pragma unroll
    for (int k = 0; k < 16; k++) {
        float4 s = make_float4(0.f, 0.f, 0.f, 0.f);
#pragma unroll
        for (int c = 0; c < KCH; c++) {
            float4 v = *(const float4*)&g_oppart[(size_t)c * Nn * Uu + (size_t)i * Uu + k * 4];
            s.x += v.x; s.y += v.y; s.z += v.z; s.w += v.w;
        }
        float4 w = pw2[k];
        dot += s.x * w.x + s.y * w.y + s.z * w.z + s.w * w.w;
    }
    float pred = dot >= 0.f ? dot : 0.2f * dot;
    float bp = base_price[i];
    g_rr[i] = (pred - bp) / bp;
}

// ---------------- K5: final losses (single block) ----------------
__global__ void k_final(const float* __restrict__ ground_truth,
                        const float* __restrict__ mask,
                        float* __restrict__ out, int out_size) {
    __shared__ float s_reg[256], s_p[256], s_n[256];
    int t = threadIdx.x;
    float reg = 0.f, p = 0.f, ng = 0.f;
    for (int i = t; i < Nn; i += 256) {
        float rr = g_rr[i];
        float d = rr - ground_truth[i];
        reg += d * d;
        float x = rr * mask[i];
        p  += fmaxf(x, 0.f);
        ng += fminf(x, 0.f);
    }
    s_reg[t] = reg; s_p[t] = p; s_n[t] = ng;
    __syncthreads();
    for (int st = 128; st > 0; st >>= 1) {
        if (t < st) {
            s_reg[t] += s_reg[t + st];
            s_p[t]   += s_p[t + st];
            s_n[t]   += s_n[t + st];
        }
        __syncthreads();
    }
    if (t == 0) {
        float regl = s_reg[0];
        float P = s_p[0], Ng = s_n[0];
        float rank = (P * P + Ng * Ng) / ((float)Nn * (float)Nn);
        float loss = regl + ALPHA * rank;
        if (out_size >= 1) out[0] = loss;
        if (out_size >= 2) out[1] = regl;
        if (out_size >= 3) out[2] = rank;
    }
}

// ---------------- launch ----------------
extern "C" void kernel_launch(void* const* d_in, const int* in_sizes, int n_in,
                              void* d_out, int out_size) {
    const float* feature      = (const float*)d_in[0];
    const float* relation     = (const float*)d_in[1];
    const float* rel_mask     = (const float*)d_in[2];
    const float* base_price   = (const float*)d_in[3];
    const float* ground_truth = (const float*)d_in[4];
    const float* mask         = (const float*)d_in[5];
    const float* rel_w        = (const float*)d_in[6];
    const float* rel_b        = (const float*)d_in[7];
    const float* head_w       = (const float*)d_in[8];
    const float* head_b       = (const float*)d_in[9];
    // tail_w/tail_b (10/11) dead: tail[j] constant per softmax column (axis 0)
    const float* pred_w       = (const float*)d_in[12];
    const float* pred_b       = (const float*)d_in[13];
    float* out = (float*)d_out;

    k_init<<<(Nn + 255) / 256, 256>>>(feature, head_w, head_b);
    {
        dim3 g(Nn / 32, Nn / 64);          // 64 x 32 = 2048 blocks
        k_rel_exp<<<g, 256>>>(relation, rel_w, rel_b, rel_mask);
    }
    {
        dim3 g(Nn / 64, KCH);              // 32 x 8 = 256 blocks
        k_gemm<<<g, 256>>>(feature);
    }
    k_pred<<<(Nn + 255) / 256, 256>>>(feature, pred_w, pred_b, base_price);
    k_final<<<1, 256>>>(ground_truth, mask, out, out_size);
}

// round 8
// speedup vs baseline: 1.3022x; 1.0833x over previous
#include <cuda_runtime.h>
#include <math.h>

#define Nn 2048
#define Uu 64
#define ALPHA 1.0f
#define KCH 8             // split-K chunks in the aggregation GEMM

// ---------------- scratch (no allocations allowed) ----------------
__device__ float g_L[(size_t)Nn * Nn];                 // 16 MB: E = exp(logits)
__device__ float g_colpart[32 * Nn];                   // partial column sums
__device__ float g_head[Nn];
__device__ float g_oppart[KCH * (size_t)Nn * Uu];      // split-K partials (4 MB)
__device__ float g_rr[Nn];                             // return ratio per row

// ---------------- K1: head scores ----------------
__global__ void k_init(const float* __restrict__ feature,
                       const float* __restrict__ head_w,
                       const float* __restrict__ head_b) {
    int i = blockIdx.x * blockDim.x + threadIdx.x;
    if (i >= Nn) return;
    const float4* fr = (const float4*)(feature + (size_t)i * Uu);
    const float4* hw = (const float4*)head_w;
    float4 a4 = make_float4(0.f, 0.f, 0.f, 0.f);
#pragma unroll
    for (int k = 0; k < 16; k++) {
        float4 a = fr[k], w = hw[k];
        a4.x += a.x * w.x; a4.y += a.y * w.y; a4.z += a.z * w.z; a4.w += a.w * w.w;
    }
    g_head[i] = fmaxf((a4.x + a4.y) + (a4.z + a4.w) + head_b[0], 0.f);
}

// ---------------- K2: 1 GiB stream, warp-cooperative, fused exp + colsum ----
// 8 lanes per pair, 4 pairs per warp -> each warp-iteration reads 1KB
// contiguous (64 consecutive float4). No smem, no syncs in hot loop.
// E[i,j] = exp( relu(rel[i,j,:]·w + b) + mask[i,j] + head[i] )
// (max-subtraction skipped: logits bounded far below fp32 exp overflow)
__global__ void k_rel_exp(const float* __restrict__ relation,
                          const float* __restrict__ rel_w,
                          const float* __restrict__ rel_b,
                          const float* __restrict__ rel_mask) {
    __shared__ float s_head[64];
    const int t  = threadIdx.x;
    const int w  = t >> 5;          // warp in block (0-7)
    const int l  = t & 31;          // lane
    const int g  = l >> 3;          // pair group within warp (0-3)
    const int k  = l & 7;           // element slot within pair
    const int j0 = blockIdx.x * 32 + w * 4;   // warp's 4 columns
    const int i0 = blockIdx.y * 64;           // block's 64 rows

    if (t < 64) s_head[t] = g_head[i0 + t];
    __syncthreads();

    const float rb = rel_b[0];
    const float4 wa = __ldg(&((const float4*)rel_w)[k]);
    const float4 wb = __ldg(&((const float4*)rel_w)[k + 8]);

    const float4* base = (const float4*)relation + ((size_t)i0 * Nn + j0) * 16;
    const int o1 = g * 16 + k;      // lane's fixed float4 offsets in 1KB span
    const int o2 = o1 + 8;

    float colsum = 0.f;
#pragma unroll 4
    for (int r = 0; r < 64; r++) {
        const float4* rowp = base + (size_t)r * (Nn * 16);
        float4 a = rowp[o1];
        float4 b = rowp[o2];
        float d = a.x * wa.x + a.y * wa.y + a.z * wa.z + a.w * wa.w
                + b.x * wb.x + b.y * wb.y + b.z * wb.z + b.w * wb.w;
        // reduce over the 8-lane group
        d += __shfl_xor_sync(0xffffffffu, d, 1);
        d += __shfl_xor_sync(0xffffffffu, d, 2);
        d += __shfl_xor_sync(0xffffffffu, d, 4);
        // gather the 4 group sums into lanes 0-3
        float s = __shfl_sync(0xffffffffu, d, (l * 8) & 31);
        if (l < 4) {
            size_t p = (size_t)(i0 + r) * Nn + j0 + l;
            float logit = fmaxf(s + rb, 0.f) + rel_mask[p] + s_head[r];
            float e = __expf(logit);
            g_L[p] = e;
            colsum += e;
        }
    }
    if (l < 4)
        g_colpart[(size_t)blockIdx.y * Nn + j0 + l] = colsum;
}

// ---------------- K3: split-K GEMM  op = E @ (feature * colinv) ----------------
// grid (32 row-blocks, KCH j-chunks of 256), 256 threads, 64x64 block,
// 4x4 reg tiles. colinv reduced from partials in the prologue (no extra kernel).
__global__ void __launch_bounds__(256, 2) k_gemm(const float* __restrict__ feature) {
    __shared__ float Es[64][65];
    __shared__ float fs[64][68];
    __shared__ float s_cinv[256];

    const int t  = threadIdx.x;
    const int ug = t & 15;          // u0 = ug*4
    const int rg = t >> 4;          // r0 = rg*4
    const int i0 = blockIdx.x * 64;
    const int jc = blockIdx.y;

    // prologue: colinv for this block's 256 columns
    {
        int j = jc * 256 + t;
        float s = 0.f;
#pragma unroll
        for (int c = 0; c < 32; c++) s += g_colpart[(size_t)c * Nn + j];
        s_cinv[t] = 1.0f / s;
    }
    __syncthreads();

    float4 acc[4];
#pragma unroll
    for (int r = 0; r < 4; r++) acc[r] = make_float4(0.f, 0.f, 0.f, 0.f);

#pragma unroll
    for (int tile = 0; tile < 4; tile++) {
        const int j0 = jc * 256 + tile * 64;
#pragma unroll
        for (int k = 0; k < 16; k++) {
            int q = k * 256 + t;
            int r = q >> 6, c = q & 63;
            Es[r][c] = g_L[(size_t)(i0 + r) * Nn + (j0 + c)];
        }
#pragma unroll
        for (int k = 0; k < 16; k++) {
            int q = k * 256 + t;
            int jr = q >> 6, u = q & 63;
            fs[jr][u] = feature[(size_t)(j0 + jr) * Uu + u] * s_cinv[tile * 64 + jr];
        }
        __syncthreads();
#pragma unroll
        for (int jj = 0; jj < 64; jj++) {
            float4 b = *(const float4*)&fs[jj][ug * 4];
            float a0 = Es[rg * 4 + 0][jj];
            float a1 = Es[rg * 4 + 1][jj];
            float a2 = Es[rg * 4 + 2][jj];
            float a3 = Es[rg * 4 + 3][jj];
            acc[0].x += a0 * b.x; acc[0].y += a0 * b.y; acc[0].z += a0 * b.z; acc[0].w += a0 * b.w;
            acc[1].x += a1 * b.x; acc[1].y += a1 * b.y; acc[1].z += a1 * b.z; acc[1].w += a1 * b.w;
            acc[2].x += a2 * b.x; acc[2].y += a2 * b.y; acc[2].z += a2 * b.z; acc[2].w += a2 * b.w;
            acc[3].x += a3 * b.x; acc[3].y += a3 * b.y; acc[3].z += a3 * b.z; acc[3].w += a3 * b.w;
        }
        __syncthreads();
    }
    size_t base = (size_t)jc * Nn * Uu;
#pragma unroll
    for (int r = 0; r < 4; r++) {
        *(float4*)&g_oppart[base + (size_t)(i0 + rg * 4 + r) * Uu + ug * 4] = acc[r];
    }
}

// ---------------- K4: prediction + return ratio (warp per row) ----------------
// Lane l owns u-pair [2l, 2l+1]; a warp's float2 loads cover each 256B row
// contiguously. 8 independent chunk loads per lane -> deep MLP.
__global__ void k_pred(const float* __restrict__ feature,
                       const float* __restrict__ pred_w,
                       const float* __restrict__ pred_b,
                       const float* __restrict__ base_price) {
    const int warp = (blockIdx.x * blockDim.x + threadIdx.x) >> 5;
    const int l    = threadIdx.x & 31;
    if (warp >= Nn) return;
    const int i = warp;

    // feature half: dot(feature[i,:], pred_w[0:64])
    float2 f  = ((const float2*)(feature + (size_t)i * Uu))[l];
    float2 w1 = ((const float2*)pred_w)[l];
    float dot = f.x * w1.x + f.y * w1.y;

    // propagated half: sum split-K partials, dot with pred_w[64:128]
    float sx = 0.f, sy = 0.f;
#pragma unroll
    for (int c = 0; c < KCH; c++) {
        float2 v = ((const float2*)(g_oppart + (size_t)c * Nn * Uu + (size_t)i * Uu))[l];
        sx += v.x; sy += v.y;
    }
    float2 w2 = ((const float2*)(pred_w + Uu))[l];
    dot += sx * w2.x + sy * w2.y;

#pragma unroll
    for (int o = 16; o > 0; o >>= 1)
        dot += __shfl_xor_sync(0xffffffffu, dot, o);

    if (l == 0) {
        dot += pred_b[0];
        float pred = dot >= 0.f ? dot : 0.2f * dot;
        float bp = base_price[i];
        g_rr[i] = (pred - bp) / bp;
    }
}

// ---------------- K5: final losses (single block) ----------------
__global__ void k_final(const float* __restrict__ ground_truth,
                        const float* __restrict__ mask,
                        float* __restrict__ out, int out_size) {
    __shared__ float s_reg[256], s_p[256], s_n[256];
    int t = threadIdx.x;
    float reg = 0.f, p = 0.f, ng = 0.f;
    for (int i = t; i < Nn; i += 256) {
        float rr = g_rr[i];
        float d = rr - ground_truth[i];
        reg += d * d;
        float x = rr * mask[i];
        p  += fmaxf(x, 0.f);
        ng += fminf(x, 0.f);
    }
    s_reg[t] = reg; s_p[t] = p; s_n[t] = ng;
    __syncthreads();
    for (int st = 128; st > 0; st >>= 1) {
        if (t < st) {
            s_reg[t] += s_reg[t + st];
            s_p[t]   += s_p[t + st];
            s_n[t]   += s_n[t + st];
        }
        __syncthreads();
    }
    if (t == 0) {
        float regl = s_reg[0];
        float P = s_p[0], Ng = s_n[0];
        float rank = (P * P + Ng * Ng) / ((float)Nn * (float)Nn);
        float loss = regl + ALPHA * rank;
        if (out_size >= 1) out[0] = loss;
        if (out_size >= 2) out[1] = regl;
        if (out_size >= 3) out[2] = rank;
    }
}

// ---------------- launch ----------------
extern "C" void kernel_launch(void* const* d_in, const int* in_sizes, int n_in,
                              void* d_out, int out_size) {
    const float* feature      = (const float*)d_in[0];
    const float* relation     = (const float*)d_in[1];
    const float* rel_mask     = (const float*)d_in[2];
    const float* base_price   = (const float*)d_in[3];
    const float* ground_truth = (const float*)d_in[4];
    const float* mask         = (const float*)d_in[5];
    const float* rel_w        = (const float*)d_in[6];
    const float* rel_b        = (const float*)d_in[7];
    const float* head_w       = (const float*)d_in[8];
    const float* head_b       = (const float*)d_in[9];
    // tail_w/tail_b (10/11) dead: tail[j] constant per softmax column (axis 0)
    const float* pred_w       = (const float*)d_in[12];
    const float* pred_b       = (const float*)d_in[13];
    float* out = (float*)d_out;

    k_init<<<(Nn + 255) / 256, 256>>>(feature, head_w, head_b);
    {
        dim3 g(Nn / 32, Nn / 64);          // 64 x 32 = 2048 blocks
        k_rel_exp<<<g, 256>>>(relation, rel_w, rel_b, rel_mask);
    }
    {
        dim3 g(Nn / 64, KCH);              // 32 x 8 = 256 blocks
        k_gemm<<<g, 256>>>(feature);
    }
    k_pred<<<Nn / 8, 256>>>(feature, pred_w, pred_b, base_price);  // warp per row
    k_final<<<1, 256>>>(ground_truth, mask, out, out_size);
}

// round 9
// speedup vs baseline: 1.3620x; 1.0460x over previous
#include <cuda_runtime.h>
#include <math.h>

#define Nn 2048
#define Uu 64
#define ALPHA 1.0f
#define KCH 8             // split-K chunks in the aggregation GEMM

// ---------------- scratch (no allocations allowed) ----------------
__device__ float g_L[(size_t)Nn * Nn];                 // 16 MB: E = exp(logits)
__device__ float g_colpart[32 * Nn];                   // partial column sums
__device__ float g_head[Nn];
__device__ float g_oppart[KCH * (size_t)Nn * Uu];      // split-K partials (4 MB)
__device__ float g_rr[Nn];                             // return ratio per row
__device__ int   g_ctr;                                // completion ticket

// ---------------- K1: head scores (+ ticket reset) ----------------
__global__ void k_init(const float* __restrict__ feature,
                       const float* __restrict__ head_w,
                       const float* __restrict__ head_b) {
    int i = blockIdx.x * blockDim.x + threadIdx.x;
    if (i == 0) g_ctr = 0;
    if (i >= Nn) return;
    const float4* fr = (const float4*)(feature + (size_t)i * Uu);
    const float4* hw = (const float4*)head_w;
    float4 a4 = make_float4(0.f, 0.f, 0.f, 0.f);
#pragma unroll
    for (int k = 0; k < 16; k++) {
        float4 a = fr[k], w = hw[k];
        a4.x += a.x * w.x; a4.y += a.y * w.y; a4.z += a.z * w.z; a4.w += a.w * w.w;
    }
    g_head[i] = fmaxf((a4.x + a4.y) + (a4.z + a4.w) + head_b[0], 0.f);
}

// ---------------- K2: 1 GiB stream, warp-cooperative, fused exp + colsum ----
// 8 lanes per pair, 4 pairs per warp -> each warp-iteration reads 1KB
// contiguous (64 consecutive float4). No smem, no syncs in hot loop.
// E[i,j] = exp( relu(rel[i,j,:]·w + b) + mask[i,j] + head[i] )
// (max-subtraction skipped: logits bounded far below fp32 exp overflow)
__global__ void k_rel_exp(const float* __restrict__ relation,
                          const float* __restrict__ rel_w,
                          const float* __restrict__ rel_b,
                          const float* __restrict__ rel_mask) {
    __shared__ float s_head[64];
    const int t  = threadIdx.x;
    const int w  = t >> 5;          // warp in block (0-7)
    const int l  = t & 31;          // lane
    const int g  = l >> 3;          // pair group within warp (0-3)
    const int k  = l & 7;           // element slot within pair
    const int j0 = blockIdx.x * 32 + w * 4;   // warp's 4 columns
    const int i0 = blockIdx.y * 64;           // block's 64 rows

    if (t < 64) s_head[t] = g_head[i0 + t];
    __syncthreads();

    const float rb = rel_b[0];
    const float4 wa = __ldg(&((const float4*)rel_w)[k]);
    const float4 wb = __ldg(&((const float4*)rel_w)[k + 8]);

    const float4* base = (const float4*)relation + ((size_t)i0 * Nn + j0) * 16;
    const int o1 = g * 16 + k;      // lane's fixed float4 offsets in 1KB span
    const int o2 = o1 + 8;

    float colsum = 0.f;
#pragma unroll 8
    for (int r = 0; r < 64; r++) {
        const float4* rowp = base + (size_t)r * (Nn * 16);
        float4 a = rowp[o1];
        float4 b = rowp[o2];
        float d = a.x * wa.x + a.y * wa.y + a.z * wa.z + a.w * wa.w
                + b.x * wb.x + b.y * wb.y + b.z * wb.z + b.w * wb.w;
        // reduce over the 8-lane group
        d += __shfl_xor_sync(0xffffffffu, d, 1);
        d += __shfl_xor_sync(0xffffffffu, d, 2);
        d += __shfl_xor_sync(0xffffffffu, d, 4);
        // gather the 4 group sums into lanes 0-3
        float s = __shfl_sync(0xffffffffu, d, (l * 8) & 31);
        if (l < 4) {
            size_t p = (size_t)(i0 + r) * Nn + j0 + l;
            float logit = fmaxf(s + rb, 0.f) + rel_mask[p] + s_head[r];
            float e = __expf(logit);
            g_L[p] = e;
            colsum += e;
        }
    }
    if (l < 4)
        g_colpart[(size_t)blockIdx.y * Nn + j0 + l] = colsum;
}

// ---------------- K3: split-K GEMM  op = E @ (feature * colinv) ----------------
// grid (32 row-blocks, KCH j-chunks of 256), 256 threads, 64x64 block,
// 4x4 reg tiles. colinv reduced from partials in the prologue (no extra kernel).
__global__ void __launch_bounds__(256, 3) k_gemm(const float* __restrict__ feature) {
    __shared__ float Es[64][65];
    __shared__ float fs[64][68];
    __shared__ float s_cinv[256];

    const int t  = threadIdx.x;
    const int ug = t & 15;          // u0 = ug*4
    const int rg = t >> 4;          // r0 = rg*4
    const int i0 = blockIdx.x * 64;
    const int jc = blockIdx.y;

    // prologue: colinv for this block's 256 columns
    {
        int j = jc * 256 + t;
        float s = 0.f;
#pragma unroll
        for (int c = 0; c < 32; c++) s += g_colpart[(size_t)c * Nn + j];
        s_cinv[t] = 1.0f / s;
    }
    __syncthreads();

    float4 acc[4];
#pragma unroll
    for (int r = 0; r < 4; r++) acc[r] = make_float4(0.f, 0.f, 0.f, 0.f);

#pragma unroll
    for (int tile = 0; tile < 4; tile++) {
        const int j0 = jc * 256 + tile * 64;
#pragma unroll
        for (int k = 0; k < 16; k++) {
            int q = k * 256 + t;
            int r = q >> 6, c = q & 63;
            Es[r][c] = g_L[(size_t)(i0 + r) * Nn + (j0 + c)];
        }
#pragma unroll
        for (int k = 0; k < 16; k++) {
            int q = k * 256 + t;
            int jr = q >> 6, u = q & 63;
            fs[jr][u] = feature[(size_t)(j0 + jr) * Uu + u] * s_cinv[tile * 64 + jr];
        }
        __syncthreads();
#pragma unroll
        for (int jj = 0; jj < 64; jj++) {
            float4 b = *(const float4*)&fs[jj][ug * 4];
            float a0 = Es[rg * 4 + 0][jj];
            float a1 = Es[rg * 4 + 1][jj];
            float a2 = Es[rg * 4 + 2][jj];
            float a3 = Es[rg * 4 + 3][jj];
            acc[0].x += a0 * b.x; acc[0].y += a0 * b.y; acc[0].z += a0 * b.z; acc[0].w += a0 * b.w;
            acc[1].x += a1 * b.x; acc[1].y += a1 * b.y; acc[1].z += a1 * b.z; acc[1].w += a1 * b.w;
            acc[2].x += a2 * b.x; acc[2].y += a2 * b.y; acc[2].z += a2 * b.z; acc[2].w += a2 * b.w;
            acc[3].x += a3 * b.x; acc[3].y += a3 * b.y; acc[3].z += a3 * b.z; acc[3].w += a3 * b.w;
        }
        __syncthreads();
    }
    size_t base = (size_t)jc * Nn * Uu;
#pragma unroll
    for (int r = 0; r < 4; r++) {
        *(float4*)&g_oppart[base + (size_t)(i0 + rg * 4 + r) * Uu + ug * 4] = acc[r];
    }
}

// ---------------- K4: prediction + return ratio + fused final losses -------
// Warp per row; last-arriving block computes the loss reduction (fixed order,
// single block -> deterministic).
__global__ void k_pred(const float* __restrict__ feature,
                       const float* __restrict__ pred_w,
                       const float* __restrict__ pred_b,
                       const float* __restrict__ base_price,
                       const float* __restrict__ ground_truth,
                       const float* __restrict__ mask,
                       float* __restrict__ out, int out_size) {
    const int warp = (blockIdx.x * blockDim.x + threadIdx.x) >> 5;
    const int l    = threadIdx.x & 31;
    const int i    = warp;

    if (i < Nn) {
        // feature half: dot(feature[i,:], pred_w[0:64])
        float2 f  = ((const float2*)(feature + (size_t)i * Uu))[l];
        float2 w1 = ((const float2*)pred_w)[l];
        float dot = f.x * w1.x + f.y * w1.y;

        // propagated half: sum split-K partials, dot with pred_w[64:128]
        float sx = 0.f, sy = 0.f;
#pragma unroll
        for (int c = 0; c < KCH; c++) {
            float2 v = ((const float2*)(g_oppart + (size_t)c * Nn * Uu + (size_t)i * Uu))[l];
            sx += v.x; sy += v.y;
        }
        float2 w2 = ((const float2*)(pred_w + Uu))[l];
        dot += sx * w2.x + sy * w2.y;

#pragma unroll
        for (int o = 16; o > 0; o >>= 1)
            dot += __shfl_xor_sync(0xffffffffu, dot, o);

        if (l == 0) {
            dot += pred_b[0];
            float pred = dot >= 0.f ? dot : 0.2f * dot;
            float bp = base_price[i];
            g_rr[i] = (pred - bp) / bp;
        }
    }

    // ---- completion ticket: last block does the final reduction ----
    __threadfence();
    __syncthreads();
    __shared__ int s_last;
    if (threadIdx.x == 0)
        s_last = (atomicAdd(&g_ctr, 1) == (int)gridDim.x - 1);
    __syncthreads();
    if (!s_last) return;

    __shared__ float s_reg[256], s_p[256], s_n[256];
    const int t = threadIdx.x;
    float reg = 0.f, p = 0.f, ng = 0.f;
    for (int r = t; r < Nn; r += 256) {
        float rr = g_rr[r];
        float d = rr - ground_truth[r];
        reg += d * d;
        float x = rr * mask[r];
        p  += fmaxf(x, 0.f);
        ng += fminf(x, 0.f);
    }
    s_reg[t] = reg; s_p[t] = p; s_n[t] = ng;
    __syncthreads();
    for (int st = 128; st > 0; st >>= 1) {
        if (t < st) {
            s_reg[t] += s_reg[t + st];
            s_p[t]   += s_p[t + st];
            s_n[t]   += s_n[t + st];
        }
        __syncthreads();
    }
    if (t == 0) {
        float regl = s_reg[0];
        float P = s_p[0], Ng = s_n[0];
        float rank = (P * P + Ng * Ng) / ((float)Nn * (float)Nn);
        float loss = regl + ALPHA * rank;
        if (out_size >= 1) out[0] = loss;
        if (out_size >= 2) out[1] = regl;
        if (out_size >= 3) out[2] = rank;
    }
}

// ---------------- launch ----------------
extern "C" void kernel_launch(void* const* d_in, const int* in_sizes, int n_in,
                              void* d_out, int out_size) {
    const float* feature      = (const float*)d_in[0];
    const float* relation     = (const float*)d_in[1];
    const float* rel_mask     = (const float*)d_in[2];
    const float* base_price   = (const float*)d_in[3];
    const float* ground_truth = (const float*)d_in[4];
    const float* mask         = (const float*)d_in[5];
    const float* rel_w        = (const float*)d_in[6];
    const float* rel_b        = (const float*)d_in[7];
    const float* head_w       = (const float*)d_in[8];
    const float* head_b       = (const float*)d_in[9];
    // tail_w/tail_b (10/11) dead: tail[j] constant per softmax column (axis 0)
    const float* pred_w       = (const float*)d_in[12];
    const float* pred_b       = (const float*)d_in[13];
    float* out = (float*)d_out;

    k_init<<<(Nn + 255) / 256, 256>>>(feature, head_w, head_b);
    {
        dim3 g(Nn / 32, Nn / 64);          // 64 x 32 = 2048 blocks
        k_rel_exp<<<g, 256>>>(relation, rel_w, rel_b, rel_mask);
    }
    {
        dim3 g(Nn / 64, KCH);              // 32 x 8 = 256 blocks
        k_gemm<<<g, 256>>>(feature);
    }
    k_pred<<<Nn / 8, 256>>>(feature, pred_w, pred_b, base_price,
                            ground_truth, mask, out, out_size);
}

// round 10
// speedup vs baseline: 1.4925x; 1.0958x over previous
#include <cuda_runtime.h>
#include <math.h>

#define Nn 2048
#define Uu 64
#define ALPHA 1.0f

// ---------------- scratch (no allocations allowed) ----------------
__device__ float g_L[(size_t)Nn * Nn];                 // 16 MB: E = exp(logits)
__device__ float g_colpart[32 * Nn];                   // partial column sums
__device__ float g_head[Nn];
__device__ float g_c[Nn];                              // c[j] = (f[j]·w2)/S_j
__device__ float g_rr[Nn];                             // return ratio per row
__device__ int   g_ctr;                                // completion ticket

// ---------------- K1: head scores (+ ticket reset) ----------------
__global__ void k_init(const float* __restrict__ feature,
                       const float* __restrict__ head_w,
                       const float* __restrict__ head_b) {
    int i = blockIdx.x * blockDim.x + threadIdx.x;
    if (i == 0) g_ctr = 0;
    if (i >= Nn) return;
    const float4* fr = (const float4*)(feature + (size_t)i * Uu);
    const float4* hw = (const float4*)head_w;
    float4 a4 = make_float4(0.f, 0.f, 0.f, 0.f);
#pragma unroll
    for (int k = 0; k < 16; k++) {
        float4 a = fr[k], w = hw[k];
        a4.x += a.x * w.x; a4.y += a.y * w.y; a4.z += a.z * w.z; a4.w += a.w * w.w;
    }
    g_head[i] = fmaxf((a4.x + a4.y) + (a4.z + a4.w) + head_b[0], 0.f);
}

// ---------------- K2: 1 GiB stream, warp-cooperative, fused exp + colsum ----
// 8 lanes per pair, 4 pairs per warp -> each warp-iteration reads 1KB
// contiguous (64 consecutive float4). No smem, no syncs in hot loop.
// E[i,j] = exp( relu(rel[i,j,:]·w + b) + mask[i,j] + head[i] )
// (max-subtraction skipped: logits bounded far below fp32 exp overflow)
__global__ void k_rel_exp(const float* __restrict__ relation,
                          const float* __restrict__ rel_w,
                          const float* __restrict__ rel_b,
                          const float* __restrict__ rel_mask) {
    __shared__ float s_head[64];
    const int t  = threadIdx.x;
    const int w  = t >> 5;          // warp in block (0-7)
    const int l  = t & 31;          // lane
    const int g  = l >> 3;          // pair group within warp (0-3)
    const int k  = l & 7;           // element slot within pair
    const int j0 = blockIdx.x * 32 + w * 4;   // warp's 4 columns
    const int i0 = blockIdx.y * 64;           // block's 64 rows

    if (t < 64) s_head[t] = g_head[i0 + t];
    __syncthreads();

    const float rb = rel_b[0];
    const float4 wa = __ldg(&((const float4*)rel_w)[k]);
    const float4 wb = __ldg(&((const float4*)rel_w)[k + 8]);

    const float4* base = (const float4*)relation + ((size_t)i0 * Nn + j0) * 16;
    const int o1 = g * 16 + k;      // lane's fixed float4 offsets in 1KB span
    const int o2 = o1 + 8;

    float colsum = 0.f;
#pragma unroll 8
    for (int r = 0; r < 64; r++) {
        const float4* rowp = base + (size_t)r * (Nn * 16);
        float4 a = rowp[o1];
        float4 b = rowp[o2];
        float d = a.x * wa.x + a.y * wa.y + a.z * wa.z + a.w * wa.w
                + b.x * wb.x + b.y * wb.y + b.z * wb.z + b.w * wb.w;
        // reduce over the 8-lane group
        d += __shfl_xor_sync(0xffffffffu, d, 1);
        d += __shfl_xor_sync(0xffffffffu, d, 2);
        d += __shfl_xor_sync(0xffffffffu, d, 4);
        // gather the 4 group sums into lanes 0-3
        float s = __shfl_sync(0xffffffffu, d, (l * 8) & 31);
        if (l < 4) {
            size_t p = (size_t)(i0 + r) * Nn + j0 + l;
            float logit = fmaxf(s + rb, 0.f) + rel_mask[p] + s_head[r];
            float e = __expf(logit);
            g_L[p] = e;
            colsum += e;
        }
    }
    if (l < 4)
        g_colpart[(size_t)blockIdx.y * Nn + j0 + l] = colsum;
}

// ---------------- K3: c[j] = (feature[j,:]·pred_w[64:128]) / S_j ------------
// op[i,:]·w2 == Σ_j (E[i,j]/S_j)(f[j,:]·w2): the aggregation GEMM collapses
// to a matvec, so only this scalar per column is needed.
__global__ void k_colc(const float* __restrict__ feature,
                       const float* __restrict__ pred_w) {
    int j = blockIdx.x * blockDim.x + threadIdx.x;
    if (j >= Nn) return;
    float s = 0.f;
#pragma unroll
    for (int c = 0; c < 32; c++) s += g_colpart[(size_t)c * Nn + j];
    const float4* fr = (const float4*)(feature + (size_t)j * Uu);
    const float4* w2 = (const float4*)(pred_w + Uu);
    float4 a4 = make_float4(0.f, 0.f, 0.f, 0.f);
#pragma unroll
    for (int k = 0; k < 16; k++) {
        float4 a = fr[k], w = w2[k];
        a4.x += a.x * w.x; a4.y += a.y * w.y; a4.z += a.z * w.z; a4.w += a.w * w.w;
    }
    g_c[j] = ((a4.x + a4.y) + (a4.z + a4.w)) / s;
}

// ---------------- K4: prediction matvec + return ratio + fused losses ------
// Warp per row: stream E[i,:] (8KB, coalesced float4) against c[:], add the
// lane-sliced feature·w1 term, one shfl reduce. Last block reduces the losses
// (fixed order, single block -> deterministic).
__global__ void k_dotpred(const float* __restrict__ feature,
                          const float* __restrict__ pred_w,
                          const float* __restrict__ pred_b,
                          const float* __restrict__ base_price,
                          const float* __restrict__ ground_truth,
                          const float* __restrict__ mask,
                          float* __restrict__ out, int out_size) {
    const int warp = (blockIdx.x * blockDim.x + threadIdx.x) >> 5;
    const int l    = threadIdx.x & 31;
    const int i    = warp;

    if (i < Nn) {
        const float4* Er = (const float4*)(g_L + (size_t)i * Nn);
        const float4* cp = (const float4*)g_c;
        float acc = 0.f;
#pragma unroll
        for (int it = 0; it < 16; it++) {
            int idx = it * 32 + l;
            float4 e = Er[idx];
            float4 c = cp[idx];
            acc += e.x * c.x + e.y * c.y + e.z * c.z + e.w * c.w;
        }
        // feature half: lane l owns u-pair [2l, 2l+1]
        float2 f  = ((const float2*)(feature + (size_t)i * Uu))[l];
        float2 w1 = ((const float2*)pred_w)[l];
        acc += f.x * w1.x + f.y * w1.y;

#pragma unroll
        for (int o = 16; o > 0; o >>= 1)
            acc += __shfl_xor_sync(0xffffffffu, acc, o);

        if (l == 0) {
            acc += pred_b[0];
            float pred = acc >= 0.f ? acc : 0.2f * acc;
            float bp = base_price[i];
            g_rr[i] = (pred - bp) / bp;
        }
    }

    // ---- completion ticket: last block does the final reduction ----
    __threadfence();
    __syncthreads();
    __shared__ int s_last;
    if (threadIdx.x == 0)
        s_last = (atomicAdd(&g_ctr, 1) == (int)gridDim.x - 1);
    __syncthreads();
    if (!s_last) return;

    __shared__ float s_reg[256], s_p[256], s_n[256];
    const int t = threadIdx.x;
    float reg = 0.f, p = 0.f, ng = 0.f;
    for (int r = t; r < Nn; r += 256) {
        float rr = g_rr[r];
        float d = rr - ground_truth[r];
        reg += d * d;
        float x = rr * mask[r];
        p  += fmaxf(x, 0.f);
        ng += fminf(x, 0.f);
    }
    s_reg[t] = reg; s_p[t] = p; s_n[t] = ng;
    __syncthreads();
    for (int st = 128; st > 0; st >>= 1) {
        if (t < st) {
            s_reg[t] += s_reg[t + st];
            s_p[t]   += s_p[t + st];
            s_n[t]   += s_n[t + st];
        }
        __syncthreads();
    }
    if (t == 0) {
        float regl = s_reg[0];
        float P = s_p[0], Ng = s_n[0];
        float rank = (P * P + Ng * Ng) / ((float)Nn * (float)Nn);
        float loss = regl + ALPHA * rank;
        if (out_size >= 1) out[0] = loss;
        if (out_size >= 2) out[1] = regl;
        if (out_size >= 3) out[2] = rank;
    }
}

// ---------------- launch ----------------
extern "C" void kernel_launch(void* const* d_in, const int* in_sizes, int n_in,
                              void* d_out, int out_size) {
    const float* feature      = (const float*)d_in[0];
    const float* relation     = (const float*)d_in[1];
    const float* rel_mask     = (const float*)d_in[2];
    const float* base_price   = (const float*)d_in[3];
    const float* ground_truth = (const float*)d_in[4];
    const float* mask         = (const float*)d_in[5];
    const float* rel_w        = (const float*)d_in[6];
    const float* rel_b        = (const float*)d_in[7];
    const float* head_w       = (const float*)d_in[8];
    const float* head_b       = (const float*)d_in[9];
    // tail_w/tail_b (10/11) dead: tail[j] constant per softmax column (axis 0)
    const float* pred_w       = (const float*)d_in[12];
    const float* pred_b       = (const float*)d_in[13];
    float* out = (float*)d_out;

    k_init<<<(Nn + 255) / 256, 256>>>(feature, head_w, head_b);
    {
        dim3 g(Nn / 32, Nn / 64);          // 64 x 32 = 2048 blocks
        k_rel_exp<<<g, 256>>>(relation, rel_w, rel_b, rel_mask);
    }
    k_colc<<<(Nn + 255) / 256, 256>>>(feature, pred_w);
    k_dotpred<<<Nn / 8, 256>>>(feature, pred_w, pred_b, base_price,
                               ground_truth, mask, out, out_size);
}

// round 12
// speedup vs baseline: 1.5752x; 1.0554x over previous
#include <cuda_runtime.h>
#include <math.h>

#define Nn 2048
#define Uu 64
#define ALPHA 1.0f

// ---------------- scratch (no allocations allowed) ----------------
__device__ float g_L[(size_t)Nn * Nn];                 // 16 MB: E = exp(logits)
__device__ float g_colpart[32 * Nn];                   // partial column sums
__device__ float g_head[Nn];
__device__ float g_c[Nn];                              // c[j] = (f[j]·w2)/S_j
__device__ float g_rr[Nn];                             // return ratio per row
__device__ int   g_ctr;                                // completion ticket

// ---------------- K1: head scores (+ ticket reset) ----------------
__global__ void k_init(const float* __restrict__ feature,
                       const float* __restrict__ head_w,
                       const float* __restrict__ head_b) {
    int i = blockIdx.x * blockDim.x + threadIdx.x;
    if (i == 0) g_ctr = 0;
    if (i >= Nn) return;
    const float4* fr = (const float4*)(feature + (size_t)i * Uu);
    const float4* hw = (const float4*)head_w;
    float4 a4 = make_float4(0.f, 0.f, 0.f, 0.f);
#pragma unroll
    for (int k = 0; k < 16; k++) {
        float4 a = fr[k], w = hw[k];
        a4.x += a.x * w.x; a4.y += a.y * w.y; a4.z += a.z * w.z; a4.w += a.w * w.w;
    }
    g_head[i] = fmaxf((a4.x + a4.y) + (a4.z + a4.w) + head_b[0], 0.f);
}

// ---------------- K2: 1 GiB stream, warp-cooperative, fused exp + colsum ----
// 8 lanes per pair, 4 pairs per warp -> each warp-iteration reads 1KB
// contiguous (64 consecutive float4). No smem, no syncs in hot loop.
// E[i,j] = exp( relu(rel[i,j,:]·w + b) + mask[i,j] + head[i] )
// (max-subtraction skipped: logits bounded far below fp32 exp overflow)
__global__ void k_rel_exp(const float* __restrict__ relation,
                          const float* __restrict__ rel_w,
                          const float* __restrict__ rel_b,
                          const float* __restrict__ rel_mask) {
    __shared__ float s_head[64];
    const int t  = threadIdx.x;
    const int w  = t >> 5;          // warp in block (0-7)
    const int l  = t & 31;          // lane
    const int g  = l >> 3;          // pair group within warp (0-3)
    const int k  = l & 7;           // element slot within pair
    const int j0 = blockIdx.x * 32 + w * 4;   // warp's 4 columns
    const int i0 = blockIdx.y * 64;           // block's 64 rows

    if (t < 64) s_head[t] = g_head[i0 + t];
    __syncthreads();

    const float rb = rel_b[0];
    const float4 wa = __ldg(&((const float4*)rel_w)[k]);
    const float4 wb = __ldg(&((const float4*)rel_w)[k + 8]);

    const float4* base = (const float4*)relation + ((size_t)i0 * Nn + j0) * 16;
    const int o1 = g * 16 + k;      // lane's fixed float4 offsets in 1KB span
    const int o2 = o1 + 8;

    float colsum = 0.f;
#pragma unroll 8
    for (int r = 0; r < 64; r++) {
        const float4* rowp = base + (size_t)r * (Nn * 16);
        float4 a = rowp[o1];
        float4 b = rowp[o2];
        float d = a.x * wa.x + a.y * wa.y + a.z * wa.z + a.w * wa.w
                + b.x * wb.x + b.y * wb.y + b.z * wb.z + b.w * wb.w;
        // reduce over the 8-lane group
        d += __shfl_xor_sync(0xffffffffu, d, 1);
        d += __shfl_xor_sync(0xffffffffu, d, 2);
        d += __shfl_xor_sync(0xffffffffu, d, 4);
        // gather the 4 group sums into lanes 0-3
        float s = __shfl_sync(0xffffffffu, d, (l * 8) & 31);
        if (l < 4) {
            size_t p = (size_t)(i0 + r) * Nn + j0 + l;
            float logit = fmaxf(s + rb, 0.f) + rel_mask[p] + s_head[r];
            float e = __expf(logit);
            g_L[p] = e;
            colsum += e;
        }
    }
    if (l < 4)
        g_colpart[(size_t)blockIdx.y * Nn + j0 + l] = colsum;
}

// ---------------- K3: c[j] = (feature[j,:]·pred_w[64:128]) / S_j ------------
// op[i,:]·w2 == Σ_j (E[i,j]/S_j)(f[j,:]·w2): the aggregation GEMM collapses
// to a matvec, so only this scalar per column is needed.
__global__ void k_colc(const float* __restrict__ feature,
                       const float* __restrict__ pred_w) {
    int j = blockIdx.x * blockDim.x + threadIdx.x;
    if (j >= Nn) return;
    float s = 0.f;
#pragma unroll
    for (int c = 0; c < 32; c++) s += g_colpart[(size_t)c * Nn + j];
    const float4* fr = (const float4*)(feature + (size_t)j * Uu);
    const float4* w2 = (const float4*)(pred_w + Uu);
    float4 a4 = make_float4(0.f, 0.f, 0.f, 0.f);
#pragma unroll
    for (int k = 0; k < 16; k++) {
        float4 a = fr[k], w = w2[k];
        a4.x += a.x * w.x; a4.y += a.y * w.y; a4.z += a.z * w.z; a4.w += a.w * w.w;
    }
    g_c[j] = ((a4.x + a4.y) + (a4.z + a4.w)) / s;
}

// ---------------- K4: prediction matvec + return ratio + fused losses ------
// Block per row: 256 threads stream E[i,:] (8KB, coalesced) against c[:];
// warp 0 folds in the lane-sliced feature·w1 term. Shfl+smem block reduce.
// Last-arriving block computes the loss reduction (fixed order -> deterministic).
__global__ void k_dotpred(const float* __restrict__ feature,
                          const float* __restrict__ pred_w,
                          const float* __restrict__ pred_b,
                          const float* __restrict__ base_price,
                          const float* __restrict__ ground_truth,
                          const float* __restrict__ mask,
                          float* __restrict__ out, int out_size) {
    const int i = blockIdx.x;
    const int t = threadIdx.x;
    const int l = t & 31;
    const int w = t >> 5;
    __shared__ float s_part[8];

    {
        const float4* Er = (const float4*)(g_L + (size_t)i * Nn);
        const float4* cp = (const float4*)g_c;
        float4 e0 = Er[t],        c0 = cp[t];
        float4 e1 = Er[t + 256],  c1 = cp[t + 256];
        float acc = e0.x * c0.x + e0.y * c0.y + e0.z * c0.z + e0.w * c0.w
                  + e1.x * c1.x + e1.y * c1.y + e1.z * c1.z + e1.w * c1.w;
        if (w == 0) {
            // feature half: lane l owns u-pair [2l, 2l+1]
            float2 f  = ((const float2*)(feature + (size_t)i * Uu))[l];
            float2 w1 = ((const float2*)pred_w)[l];
            acc += f.x * w1.x + f.y * w1.y;
        }
#pragma unroll
        for (int o = 16; o > 0; o >>= 1)
            acc += __shfl_xor_sync(0xffffffffu, acc, o);
        if (l == 0) s_part[w] = acc;
    }
    __syncthreads();
    if (t == 0) {
        float dot = pred_b[0];
#pragma unroll
        for (int q = 0; q < 8; q++) dot += s_part[q];
        float pred = dot >= 0.f ? dot : 0.2f * dot;
        float bp = base_price[i];
        g_rr[i] = (pred - bp) / bp;
    }

    // ---- completion ticket: last block does the final reduction ----
    __threadfence();
    __syncthreads();
    __shared__ int s_last;
    if (t == 0)
        s_last = (atomicAdd(&g_ctr, 1) == (int)gridDim.x - 1);
    __syncthreads();
    if (!s_last) return;

    __shared__ float s_reg[256], s_p[256], s_n[256];
    float reg = 0.f, p = 0.f, ng = 0.f;
    for (int r = t; r < Nn; r += 256) {
        float rr = g_rr[r];
        float d = rr - ground_truth[r];
        reg += d * d;
        float x = rr * mask[r];
        p  += fmaxf(x, 0.f);
        ng += fminf(x, 0.f);
    }
    s_reg[t] = reg; s_p[t] = p; s_n[t] = ng;
    __syncthreads();
    for (int st = 128; st > 0; st >>= 1) {
        if (t < st) {
            s_reg[t] += s_reg[t + st];
            s_p[t]   += s_p[t + st];
            s_n[t]   += s_n[t + st];
        }
        __syncthreads();
    }
    if (t == 0) {
        float regl = s_reg[0];
        float P = s_p[0], Ng = s_n[0];
        float rank = (P * P + Ng * Ng) / ((float)Nn * (float)Nn);
        float loss = regl + ALPHA * rank;
        if (out_size >= 1) out[0] = loss;
        if (out_size >= 2) out[1] = regl;
        if (out_size >= 3) out[2] = rank;
    }
}

// ---------------- launch ----------------
extern "C" void kernel_launch(void* const* d_in, const int* in_sizes, int n_in,
                              void* d_out, int out_size) {
    const float* feature      = (const float*)d_in[0];
    const float* relation     = (const float*)d_in[1];
    const float* rel_mask     = (const float*)d_in[2];
    const float* base_price   = (const float*)d_in[3];
    const float* ground_truth = (const float*)d_in[4];
    const float* mask         = (const float*)d_in[5];
    const float* rel_w        = (const float*)d_in[6];
    const float* rel_b        = (const float*)d_in[7];
    const float* head_w       = (const float*)d_in[8];
    const float* head_b       = (const float*)d_in[9];
    // tail_w/tail_b (10/11) dead: tail[j] constant per softmax column (axis 0)
    const float* pred_w       = (const float*)d_in[12];
    const float* pred_b       = (const float*)d_in[13];
    float* out = (float*)d_out;

    k_init<<<(Nn + 255) / 256, 256>>>(feature, head_w, head_b);
    {
        dim3 g(Nn / 32, Nn / 64);          // 64 x 32 = 2048 blocks
        k_rel_exp<<<g, 256>>>(relation, rel_w, rel_b, rel_mask);
    }
    k_colc<<<(Nn + 255) / 256, 256>>>(feature, pred_w);
    k_dotpred<<<Nn, 256>>>(feature, pred_w, pred_b, base_price,
                           ground_truth, mask, out, out_size);
}

// round 13
// speedup vs baseline: 1.5912x; 1.0101x over previous
#include <cuda_runtime.h>
#include <cuda_bf16.h>
#include <math.h>

#define Nn 2048
#define Uu 64
#define ALPHA 1.0f

// ---------------- scratch (no allocations allowed) ----------------
__device__ __nv_bfloat16 g_Lh[(size_t)Nn * Nn];        // 8 MB: E = exp(logits), bf16
__device__ float g_colpart[32 * Nn];                   // partial column sums (fp32)
__device__ float g_head[Nn];
__device__ float g_c[Nn];                              // c[j] = (f[j]·w2)/S_j
__device__ float g_rr[Nn];                             // return ratio per row
__device__ int   g_ctr;                                // completion ticket

// ---------------- K1: head scores (+ ticket reset) ----------------
__global__ void k_init(const float* __restrict__ feature,
                       const float* __restrict__ head_w,
                       const float* __restrict__ head_b) {
    int i = blockIdx.x * blockDim.x + threadIdx.x;
    if (i == 0) g_ctr = 0;
    if (i >= Nn) return;
    const float4* fr = (const float4*)(feature + (size_t)i * Uu);
    const float4* hw = (const float4*)head_w;
    float4 a4 = make_float4(0.f, 0.f, 0.f, 0.f);
#pragma unroll
    for (int k = 0; k < 16; k++) {
        float4 a = fr[k], w = hw[k];
        a4.x += a.x * w.x; a4.y += a.y * w.y; a4.z += a.z * w.z; a4.w += a.w * w.w;
    }
    g_head[i] = fmaxf((a4.x + a4.y) + (a4.z + a4.w) + head_b[0], 0.f);
}

// ---------------- K2: 1 GiB stream, warp-cooperative, fused exp + colsum ----
// 8 lanes per pair, 4 pairs per warp -> each warp-iteration reads 1KB
// contiguous. Colsum accumulated in fp32; E stored bf16 (dot-side only).
__global__ void k_rel_exp(const float* __restrict__ relation,
                          const float* __restrict__ rel_w,
                          const float* __restrict__ rel_b,
                          const float* __restrict__ rel_mask) {
    __shared__ float s_head[64];
    const int t  = threadIdx.x;
    const int w  = t >> 5;          // warp in block (0-7)
    const int l  = t & 31;          // lane
    const int g  = l >> 3;          // pair group within warp (0-3)
    const int k  = l & 7;           // element slot within pair
    const int j0 = blockIdx.x * 32 + w * 4;   // warp's 4 columns
    const int i0 = blockIdx.y * 64;           // block's 64 rows

    if (t < 64) s_head[t] = g_head[i0 + t];
    __syncthreads();

    const float rb = rel_b[0];
    const float4 wa = __ldg(&((const float4*)rel_w)[k]);
    const float4 wb = __ldg(&((const float4*)rel_w)[k + 8]);

    const float4* base = (const float4*)relation + ((size_t)i0 * Nn + j0) * 16;
    const int o1 = g * 16 + k;      // lane's fixed float4 offsets in 1KB span
    const int o2 = o1 + 8;

    float colsum = 0.f;
#pragma unroll 8
    for (int r = 0; r < 64; r++) {
        const float4* rowp = base + (size_t)r * (Nn * 16);
        float4 a = rowp[o1];
        float4 b = rowp[o2];
        float d = a.x * wa.x + a.y * wa.y + a.z * wa.z + a.w * wa.w
                + b.x * wb.x + b.y * wb.y + b.z * wb.z + b.w * wb.w;
        d += __shfl_xor_sync(0xffffffffu, d, 1);
        d += __shfl_xor_sync(0xffffffffu, d, 2);
        d += __shfl_xor_sync(0xffffffffu, d, 4);
        float s = __shfl_sync(0xffffffffu, d, (l * 8) & 31);
        if (l < 4) {
            size_t p = (size_t)(i0 + r) * Nn + j0 + l;
            float logit = fmaxf(s + rb, 0.f) + rel_mask[p] + s_head[r];
            float e = __expf(logit);
            g_Lh[p] = __float2bfloat16_rn(e);
            colsum += e;
        }
    }
    if (l < 4)
        g_colpart[(size_t)blockIdx.y * Nn + j0 + l] = colsum;
}

// ---------------- K3: c[j] = (feature[j,:]·pred_w[64:128]) / S_j ------------
__global__ void k_colc(const float* __restrict__ feature,
                       const float* __restrict__ pred_w) {
    int j = blockIdx.x * blockDim.x + threadIdx.x;
    if (j >= Nn) return;
    float s = 0.f;
#pragma unroll
    for (int c = 0; c < 32; c++) s += g_colpart[(size_t)c * Nn + j];
    const float4* fr = (const float4*)(feature + (size_t)j * Uu);
    const float4* w2 = (const float4*)(pred_w + Uu);
    float4 a4 = make_float4(0.f, 0.f, 0.f, 0.f);
#pragma unroll
    for (int k = 0; k < 16; k++) {
        float4 a = fr[k], w = w2[k];
        a4.x += a.x * w.x; a4.y += a.y * w.y; a4.z += a.z * w.z; a4.w += a.w * w.w;
    }
    g_c[j] = ((a4.x + a4.y) + (a4.z + a4.w)) / s;
}

// ---------------- K4: prediction matvec + return ratio + fused losses ------
// 512 blocks x 4 rows. Thread t owns j-slice [8t, 8t+8): one uint4 = 8 bf16
// per row (4 independent LDG.128), c loaded once and reused. Deferred
// reductions; last block computes losses (fixed order -> deterministic).
__global__ void k_dotpred(const float* __restrict__ feature,
                          const float* __restrict__ pred_w,
                          const float* __restrict__ pred_b,
                          const float* __restrict__ base_price,
                          const float* __restrict__ ground_truth,
                          const float* __restrict__ mask,
                          float* __restrict__ out, int out_size) {
    const int i0 = blockIdx.x * 4;
    const int t  = threadIdx.x;
    const int l  = t & 31;
    const int w  = t >> 5;
    __shared__ float s_epart[4][8];

    {
        // c slice for this thread (reused across 4 rows)
        float4 c0 = ((const float4*)g_c)[2 * t];
        float4 c1 = ((const float4*)g_c)[2 * t + 1];

        float acc[4];
#pragma unroll
        for (int r = 0; r < 4; r++) {
            uint4 raw = ((const uint4*)(g_Lh + (size_t)(i0 + r) * Nn))[t];
            const __nv_bfloat162* eb = (const __nv_bfloat162*)&raw;
            float2 e0 = __bfloat1622float2(eb[0]);
            float2 e1 = __bfloat1622float2(eb[1]);
            float2 e2 = __bfloat1622float2(eb[2]);
            float2 e3 = __bfloat1622float2(eb[3]);
            acc[r] = e0.x * c0.x + e0.y * c0.y + e1.x * c0.z + e1.y * c0.w
                   + e2.x * c1.x + e2.y * c1.y + e3.x * c1.z + e3.y * c1.w;
        }
#pragma unroll
        for (int r = 0; r < 4; r++) {
#pragma unroll
            for (int o = 16; o > 0; o >>= 1)
                acc[r] += __shfl_xor_sync(0xffffffffu, acc[r], o);
        }
        if (l == 0) {
#pragma unroll
            for (int r = 0; r < 4; r++) s_epart[r][w] = acc[r];
        }
    }
    __syncthreads();

    if (w < 4) {
        // warp w finishes row i0+w
        float esum = (l < 8) ? s_epart[w][l] : 0.f;
#pragma unroll
        for (int o = 4; o > 0; o >>= 1)
            esum += __shfl_xor_sync(0xffffffffu, esum, o);
        // feature half: lane l owns u-pair [2l, 2l+1]
        float2 f  = ((const float2*)(feature + (size_t)(i0 + w) * Uu))[l];
        float2 w1 = ((const float2*)pred_w)[l];
        float facc = f.x * w1.x + f.y * w1.y;
#pragma unroll
        for (int o = 16; o > 0; o >>= 1)
            facc += __shfl_xor_sync(0xffffffffu, facc, o);
        if (l == 0) {
            float dot = esum + facc + pred_b[0];
            float pred = dot >= 0.f ? dot : 0.2f * dot;
            float bp = base_price[i0 + w];
            g_rr[i0 + w] = (pred - bp) / bp;
        }
    }

    // ---- completion ticket: last block does the final reduction ----
    __threadfence();
    __syncthreads();
    __shared__ int s_last;
    if (t == 0)
        s_last = (atomicAdd(&g_ctr, 1) == (int)gridDim.x - 1);
    __syncthreads();
    if (!s_last) return;

    __shared__ float s_reg[256], s_p[256], s_n[256];
    float reg = 0.f, p = 0.f, ng = 0.f;
    for (int r = t; r < Nn; r += 256) {
        float rr = g_rr[r];
        float d = rr - ground_truth[r];
        reg += d * d;
        float x = rr * mask[r];
        p  += fmaxf(x, 0.f);
        ng += fminf(x, 0.f);
    }
    s_reg[t] = reg; s_p[t] = p; s_n[t] = ng;
    __syncthreads();
    for (int st = 128; st > 0; st >>= 1) {
        if (t < st) {
            s_reg[t] += s_reg[t + st];
            s_p[t]   += s_p[t + st];
            s_n[t]   += s_n[t + st];
        }
        __syncthreads();
    }
    if (t == 0) {
        float regl = s_reg[0];
        float P = s_p[0], Ng = s_n[0];
        float rank = (P * P + Ng * Ng) / ((float)Nn * (float)Nn);
        float loss = regl + ALPHA * rank;
        if (out_size >= 1) out[0] = loss;
        if (out_size >= 2) out[1] = regl;
        if (out_size >= 3) out[2] = rank;
    }
}

// ---------------- launch ----------------
extern "C" void kernel_launch(void* const* d_in, const int* in_sizes, int n_in,
                              void* d_out, int out_size) {
    const float* feature      = (const float*)d_in[0];
    const float* relation     = (const float*)d_in[1];
    const float* rel_mask     = (const float*)d_in[2];
    const float* base_price   = (const float*)d_in[3];
    const float* ground_truth = (const float*)d_in[4];
    const float* mask         = (const float*)d_in[5];
    const float* rel_w        = (const float*)d_in[6];
    const float* rel_b        = (const float*)d_in[7];
    const float* head_w       = (const float*)d_in[8];
    const float* head_b       = (const float*)d_in[9];
    // tail_w/tail_b (10/11) dead: tail[j] constant per softmax column (axis 0)
    const float* pred_w       = (const float*)d_in[12];
    const float* pred_b       = (const float*)d_in[13];
    float* out = (float*)d_out;

    k_init<<<(Nn + 255) / 256, 256>>>(feature, head_w, head_b);
    {
        dim3 g(Nn / 32, Nn / 64);          // 64 x 32 = 2048 blocks
        k_rel_exp<<<g, 256>>>(relation, rel_w, rel_b, rel_mask);
    }
    k_colc<<<(Nn + 255) / 256, 256>>>(feature, pred_w);
    k_dotpred<<<Nn / 4, 256>>>(feature, pred_w, pred_b, base_price,
                               ground_truth, mask, out, out_size);
}